// round 2
// baseline (speedup 1.0000x reference)
#include <cuda_runtime.h>
#include <math.h>

#define Bb   16
#define Ff   4096
#define Qq   64
#define DIMc 512
#define Hh   8
#define DHh  64

// ---------------- scratch (device globals; no allocation allowed) ----------------
__device__ float g_xn  [(size_t)Bb * Ff * DIMc];   // LN(features)
__device__ float g_latn[(size_t)Bb * Qq * DIMc];   // LN(latents)
__device__ float g_q   [(size_t)Bb * Qq * DIMc];
__device__ float g_k   [(size_t)Bb * Ff * DIMc];
__device__ float g_v   [(size_t)Bb * Ff * DIMc];
__device__ float g_att [(size_t)Bb * Qq * DIMc];
__device__ float g_ln2 [(size_t)Bb * Qq * DIMc];
__device__ float g_ffh [(size_t)Bb * Qq * 1024];

// ---------------- LayerNorm: one block (128 threads) per row of 512 ----------------
__global__ void ln_kernel(const float* __restrict__ x, const float* __restrict__ g,
                          const float* __restrict__ beta, float* __restrict__ y) {
    __shared__ float sm[4];
    size_t row = blockIdx.x;
    int t = threadIdx.x;                       // 0..127, each owns a float4
    float4 v = ((const float4*)(x + row * DIMc))[t];
    float s = v.x + v.y + v.z + v.w;
    #pragma unroll
    for (int o = 16; o; o >>= 1) s += __shfl_xor_sync(0xffffffffu, s, o);
    if ((t & 31) == 0) sm[t >> 5] = s;
    __syncthreads();
    float mean = (sm[0] + sm[1] + sm[2] + sm[3]) * (1.0f / DIMc);
    __syncthreads();
    float dx = v.x - mean, dy = v.y - mean, dz = v.z - mean, dw = v.w - mean;
    float sq = dx * dx + dy * dy + dz * dz + dw * dw;
    #pragma unroll
    for (int o = 16; o; o >>= 1) sq += __shfl_xor_sync(0xffffffffu, sq, o);
    if ((t & 31) == 0) sm[t >> 5] = sq;
    __syncthreads();
    float var = (sm[0] + sm[1] + sm[2] + sm[3]) * (1.0f / DIMc);
    float rstd = rsqrtf(var + 1e-5f);
    float4 gg = ((const float4*)g)[t];
    float4 bb = ((const float4*)beta)[t];
    float4 o4;
    o4.x = dx * rstd * gg.x + bb.x;
    o4.y = dy * rstd * gg.y + bb.y;
    o4.z = dz * rstd * gg.z + bb.z;
    o4.w = dw * rstd * gg.w + bb.w;
    ((float4*)(y + row * DIMc))[t] = o4;
}

// ---------------- SGEMM: C[M,N] = A[M,K] @ W[K,N] (row-major), 64x64 tile ----------------
// 256 threads, 4x4 per-thread microtile, TK=16. M%64==0, N%64==0, K%16==0.
__global__ void sgemm64(const float* __restrict__ A, const float* __restrict__ W,
                        float* __restrict__ C, int M, int N, int K, int relu) {
    __shared__ __align__(16) float As[16][64];
    __shared__ __align__(16) float Bs[16][64];
    int tid = threadIdx.x;
    int tx = tid & 15, ty = tid >> 4;
    int bm = blockIdx.y << 6, bn = blockIdx.x << 6;

    float acc[4][4];
    #pragma unroll
    for (int i = 0; i < 4; i++)
        #pragma unroll
        for (int j = 0; j < 4; j++) acc[i][j] = 0.f;

    int am  = tid >> 2;          // 0..63 row in A tile
    int ak  = (tid & 3) << 2;    // 0,4,8,12 k offset
    int bk  = tid >> 4;          // 0..15 row in W tile
    int bn4 = (tid & 15) << 2;   // 0..60 col offset

    const float* Ap = A + (size_t)(bm + am) * K + ak;
    const float* Wp = W + (size_t)bk * N + bn + bn4;

    for (int k0 = 0; k0 < K; k0 += 16) {
        float4 a = *(const float4*)(Ap + k0);
        As[ak + 0][am] = a.x; As[ak + 1][am] = a.y;
        As[ak + 2][am] = a.z; As[ak + 3][am] = a.w;
        float4 b = *(const float4*)(Wp + (size_t)k0 * N);
        *(float4*)&Bs[bk][bn4] = b;
        __syncthreads();
        #pragma unroll
        for (int k = 0; k < 16; k++) {
            float4 ar = *(const float4*)&As[k][ty << 2];
            float4 br = *(const float4*)&Bs[k][tx << 2];
            float arr[4] = {ar.x, ar.y, ar.z, ar.w};
            float brr[4] = {br.x, br.y, br.z, br.w};
            #pragma unroll
            for (int i = 0; i < 4; i++)
                #pragma unroll
                for (int j = 0; j < 4; j++)
                    acc[i][j] += arr[i] * brr[j];
        }
        __syncthreads();
    }
    #pragma unroll
    for (int i = 0; i < 4; i++) {
        float4 o;
        o.x = acc[i][0]; o.y = acc[i][1]; o.z = acc[i][2]; o.w = acc[i][3];
        if (relu) {
            o.x = fmaxf(o.x, 0.f); o.y = fmaxf(o.y, 0.f);
            o.z = fmaxf(o.z, 0.f); o.w = fmaxf(o.w, 0.f);
        }
        *(float4*)(C + (size_t)(bm + (ty << 2) + i) * N + bn + (tx << 2)) = o;
    }
}

// ---------------- block reductions over 256 threads ----------------
__device__ __forceinline__ float blockMax256(float v, float* sm) {
    #pragma unroll
    for (int o = 16; o; o >>= 1) v = fmaxf(v, __shfl_xor_sync(0xffffffffu, v, o));
    if ((threadIdx.x & 31) == 0) sm[threadIdx.x >> 5] = v;
    __syncthreads();
    float r = sm[0];
    #pragma unroll
    for (int i = 1; i < 8; i++) r = fmaxf(r, sm[i]);
    __syncthreads();
    return r;
}
__device__ __forceinline__ float blockSum256(float v, float* sm) {
    #pragma unroll
    for (int o = 16; o; o >>= 1) v += __shfl_xor_sync(0xffffffffu, v, o);
    if ((threadIdx.x & 31) == 0) sm[threadIdx.x >> 5] = v;
    __syncthreads();
    float r = 0.f;
    #pragma unroll
    for (int i = 0; i < 8; i++) r += sm[i];
    __syncthreads();
    return r;
}

// ---------------- attention: one block (256 threads) per (b, h, q-row) ----------------
// K,V stored as (B, F, DIM) with head h occupying columns [h*64, h*64+64).
__global__ void attn_kernel(const float* __restrict__ qb, const float* __restrict__ kb,
                            const float* __restrict__ vb, const int* __restrict__ mask,
                            float* __restrict__ out) {
    __shared__ __align__(16) float qs[DHh];
    __shared__ float w[Ff];
    __shared__ float sm[8];
    __shared__ float red[256];
    int t  = threadIdx.x;
    int qi = blockIdx.x & 63;
    int h  = (blockIdx.x >> 6) & 7;
    int b  = blockIdx.x >> 9;

    if (t < DHh) qs[t] = qb[((size_t)(b * Qq + qi)) * DIMc + h * DHh + t];
    __syncthreads();

    const int* mrow = mask + (size_t)b * Ff;
    float s[16];
    float lmax = -INFINITY;
    #pragma unroll
    for (int i = 0; i < 16; i++) {
        int f = (i << 8) + t;            // 16 f-values per thread
        float sv = -INFINITY;
        if (mrow[f]) {
            const float4* kp = (const float4*)(kb + ((size_t)(b * Ff + f)) * DIMc + h * DHh);
            float acc = 0.f;
            #pragma unroll
            for (int j = 0; j < 16; j++) {
                float4 kk = kp[j];
                float4 qq = ((const float4*)qs)[j];
                acc += kk.x * qq.x + kk.y * qq.y + kk.z * qq.z + kk.w * qq.w;
            }
            sv = acc * 0.125f;           // DH^-0.5
        }
        s[i] = sv;
        lmax = fmaxf(lmax, sv);
    }
    float gmax = blockMax256(lmax, sm);
    float lsum = 0.f;
    #pragma unroll
    for (int i = 0; i < 16; i++) {
        float e = (s[i] == -INFINITY) ? 0.f : expf(s[i] - gmax);
        s[i] = e;
        lsum += e;
    }
    float gsum = blockSum256(lsum, sm);
    float inv = (gsum > 0.f) ? (1.f / gsum) : 0.f;   // nan_to_num(all-masked) -> 0
    #pragma unroll
    for (int i = 0; i < 16; i++) w[(i << 8) + t] = s[i] * inv;
    __syncthreads();

    // pass 2: thread (c, d) accumulates over its quarter of F, coalesced on d
    int d = t & 63;
    int c = t >> 6;
    const float* vp = vb + ((size_t)b * Ff) * DIMc + h * DHh + d;
    float a0 = 0.f, a1 = 0.f, a2 = 0.f, a3 = 0.f;
    int f0 = c << 10;
    for (int f = f0; f < f0 + 1024; f += 4) {
        a0 += w[f + 0] * vp[(size_t)(f + 0) * DIMc];
        a1 += w[f + 1] * vp[(size_t)(f + 1) * DIMc];
        a2 += w[f + 2] * vp[(size_t)(f + 2) * DIMc];
        a3 += w[f + 3] * vp[(size_t)(f + 3) * DIMc];
    }
    red[t] = (a0 + a1) + (a2 + a3);
    __syncthreads();
    if (t < 64) {
        float r = red[t] + red[64 + t] + red[128 + t] + red[192 + t];
        out[((size_t)(b * Qq + qi)) * DIMc + h * DHh + t] = r;
    }
}

// ---------------- launch ----------------
extern "C" void kernel_launch(void* const* d_in, const int* in_sizes, int n_in,
                              void* d_out, int out_size) {
    const float* features = (const float*)d_in[0];
    const float* latents  = (const float*)d_in[1];
    const int*   mask     = (const int*)  d_in[2];
    const float* gf  = (const float*)d_in[3];
    const float* bf  = (const float*)d_in[4];
    const float* gl  = (const float*)d_in[5];
    const float* bl  = (const float*)d_in[6];
    const float* Wq  = (const float*)d_in[7];
    const float* Wk  = (const float*)d_in[8];
    const float* Wv  = (const float*)d_in[9];
    const float* gff = (const float*)d_in[10];
    const float* bff = (const float*)d_in[11];
    const float* W1  = (const float*)d_in[12];
    const float* W2  = (const float*)d_in[13];
    float* out = (float*)d_out;

    float *xn, *latn, *q, *k, *v, *att, *ln2, *ffh;
    cudaGetSymbolAddress((void**)&xn,   g_xn);
    cudaGetSymbolAddress((void**)&latn, g_latn);
    cudaGetSymbolAddress((void**)&q,    g_q);
    cudaGetSymbolAddress((void**)&k,    g_k);
    cudaGetSymbolAddress((void**)&v,    g_v);
    cudaGetSymbolAddress((void**)&att,  g_att);
    cudaGetSymbolAddress((void**)&ln2,  g_ln2);
    cudaGetSymbolAddress((void**)&ffh,  g_ffh);

    // 1-2: layernorms
    ln_kernel<<<Bb * Ff, 128>>>(features, gf, bf, xn);
    ln_kernel<<<Bb * Qq, 128>>>(latents,  gl, bl, latn);

    // 3-5: projections
    sgemm64<<<dim3(DIMc / 64, (Bb * Qq) / 64), 256>>>(latn, Wq, q, Bb * Qq, DIMc, DIMc, 0);
    sgemm64<<<dim3(DIMc / 64, (Bb * Ff) / 64), 256>>>(xn,   Wk, k, Bb * Ff, DIMc, DIMc, 0);
    sgemm64<<<dim3(DIMc / 64, (Bb * Ff) / 64), 256>>>(xn,   Wv, v, Bb * Ff, DIMc, DIMc, 0);

    // 6: attention
    attn_kernel<<<Bb * Hh * Qq, 256>>>(q, k, v, mask, att);

    // 7-9: feed-forward
    ln_kernel<<<Bb * Qq, 128>>>(att, gff, bff, ln2);
    sgemm64<<<dim3(1024 / 64, (Bb * Qq) / 64), 256>>>(ln2, W1, ffh, Bb * Qq, 1024, DIMc, 1);
    sgemm64<<<dim3(DIMc / 64, (Bb * Qq) / 64), 256>>>(ffh, W2, out, Bb * Qq, DIMc, 1024, 0);
}

// round 3
// speedup vs baseline: 1.6100x; 1.6100x over previous
#include <cuda_runtime.h>
#include <math.h>

#define Bb   16
#define Ff   4096
#define Qq   64
#define DIMc 512
#define Hh   8
#define DHh  64
#define FCH  128   // flash attention f-chunk

// ---------------- scratch (device globals; no allocation allowed) ----------------
__device__ float g_xn  [(size_t)Bb * Ff * DIMc];
__device__ float g_latn[(size_t)Bb * Qq * DIMc];
__device__ float g_q   [(size_t)Bb * Qq * DIMc];
__device__ float g_k   [(size_t)Bb * Ff * DIMc];
__device__ float g_v   [(size_t)Bb * Ff * DIMc];
__device__ float g_att [(size_t)Bb * Qq * DIMc];
__device__ float g_ln2 [(size_t)Bb * Qq * DIMc];
__device__ float g_ffh [(size_t)Bb * Qq * 1024];

// ---------------- LayerNorm: one block (128 threads) per row of 512 ----------------
__global__ void ln_kernel(const float* __restrict__ x, const float* __restrict__ g,
                          const float* __restrict__ beta, float* __restrict__ y) {
    __shared__ float sm[4];
    size_t row = blockIdx.x;
    int t = threadIdx.x;
    float4 v = ((const float4*)(x + row * DIMc))[t];
    float s = v.x + v.y + v.z + v.w;
    #pragma unroll
    for (int o = 16; o; o >>= 1) s += __shfl_xor_sync(0xffffffffu, s, o);
    if ((t & 31) == 0) sm[t >> 5] = s;
    __syncthreads();
    float mean = (sm[0] + sm[1] + sm[2] + sm[3]) * (1.0f / DIMc);
    __syncthreads();
    float dx = v.x - mean, dy = v.y - mean, dz = v.z - mean, dw = v.w - mean;
    float sq = dx * dx + dy * dy + dz * dz + dw * dw;
    #pragma unroll
    for (int o = 16; o; o >>= 1) sq += __shfl_xor_sync(0xffffffffu, sq, o);
    if ((t & 31) == 0) sm[t >> 5] = sq;
    __syncthreads();
    float var = (sm[0] + sm[1] + sm[2] + sm[3]) * (1.0f / DIMc);
    float rstd = rsqrtf(var + 1e-5f);
    float4 gg = ((const float4*)g)[t];
    float4 bb = ((const float4*)beta)[t];
    float4 o4;
    o4.x = dx * rstd * gg.x + bb.x;
    o4.y = dy * rstd * gg.y + bb.y;
    o4.z = dz * rstd * gg.z + bb.z;
    o4.w = dw * rstd * gg.w + bb.w;
    ((float4*)(y + row * DIMc))[t] = o4;
}

// ---------------- SGEMM 128x128 tile, 8x8 microtile, BK=8, double-buffered ----------------
// 256 threads. M%128==0, N%128==0, K%8==0.
__global__ void sgemm128(const float* __restrict__ A, const float* __restrict__ W,
                         float* __restrict__ C, int M, int N, int K, int relu) {
    __shared__ __align__(16) float As[2][8][128];
    __shared__ __align__(16) float Bs[2][8][128];
    int tid = threadIdx.x;
    int tx = tid & 15, ty = tid >> 4;
    int bm = blockIdx.y << 7, bn = blockIdx.x << 7;

    float acc[8][8];
    #pragma unroll
    for (int i = 0; i < 8; i++)
        #pragma unroll
        for (int j = 0; j < 8; j++) acc[i][j] = 0.f;

    int a_m = tid >> 1;            // 0..127
    int a_k = (tid & 1) << 2;      // 0 or 4
    int b_k = tid >> 5;            // 0..7
    int b_n = (tid & 31) << 2;     // 0..124

    const float* Ap = A + (size_t)(bm + a_m) * K + a_k;
    const float* Wp = W + (size_t)b_k * N + bn + b_n;

    // preload panel 0
    float4 av = *(const float4*)Ap;
    float4 bv = *(const float4*)Wp;
    As[0][a_k + 0][a_m] = av.x; As[0][a_k + 1][a_m] = av.y;
    As[0][a_k + 2][a_m] = av.z; As[0][a_k + 3][a_m] = av.w;
    *(float4*)&Bs[0][b_k][b_n] = bv;
    __syncthreads();

    int P = K >> 3;
    for (int p = 1; p < P; p++) {
        av = *(const float4*)(Ap + (p << 3));
        bv = *(const float4*)(Wp + (size_t)(p << 3) * N);
        int rb = (p - 1) & 1;
        #pragma unroll
        for (int k = 0; k < 8; k++) {
            float4 a0 = *(const float4*)&As[rb][k][ty << 2];
            float4 a1 = *(const float4*)&As[rb][k][64 + (ty << 2)];
            float4 b0 = *(const float4*)&Bs[rb][k][tx << 2];
            float4 b1 = *(const float4*)&Bs[rb][k][64 + (tx << 2)];
            float ar[8] = {a0.x, a0.y, a0.z, a0.w, a1.x, a1.y, a1.z, a1.w};
            float br[8] = {b0.x, b0.y, b0.z, b0.w, b1.x, b1.y, b1.z, b1.w};
            #pragma unroll
            for (int i = 0; i < 8; i++)
                #pragma unroll
                for (int j = 0; j < 8; j++)
                    acc[i][j] += ar[i] * br[j];
        }
        int wb = p & 1;
        As[wb][a_k + 0][a_m] = av.x; As[wb][a_k + 1][a_m] = av.y;
        As[wb][a_k + 2][a_m] = av.z; As[wb][a_k + 3][a_m] = av.w;
        *(float4*)&Bs[wb][b_k][b_n] = bv;
        __syncthreads();
    }
    {
        int rb = (P - 1) & 1;
        #pragma unroll
        for (int k = 0; k < 8; k++) {
            float4 a0 = *(const float4*)&As[rb][k][ty << 2];
            float4 a1 = *(const float4*)&As[rb][k][64 + (ty << 2)];
            float4 b0 = *(const float4*)&Bs[rb][k][tx << 2];
            float4 b1 = *(const float4*)&Bs[rb][k][64 + (tx << 2)];
            float ar[8] = {a0.x, a0.y, a0.z, a0.w, a1.x, a1.y, a1.z, a1.w};
            float br[8] = {b0.x, b0.y, b0.z, b0.w, b1.x, b1.y, b1.z, b1.w};
            #pragma unroll
            for (int i = 0; i < 8; i++)
                #pragma unroll
                for (int j = 0; j < 8; j++)
                    acc[i][j] += ar[i] * br[j];
        }
    }

    #pragma unroll
    for (int i = 0; i < 8; i++) {
        int row = bm + ((i < 4) ? ((ty << 2) + i) : (64 + (ty << 2) + i - 4));
        #pragma unroll
        for (int jh = 0; jh < 2; jh++) {
            float4 o;
            o.x = acc[i][jh * 4 + 0]; o.y = acc[i][jh * 4 + 1];
            o.z = acc[i][jh * 4 + 2]; o.w = acc[i][jh * 4 + 3];
            if (relu) {
                o.x = fmaxf(o.x, 0.f); o.y = fmaxf(o.y, 0.f);
                o.z = fmaxf(o.z, 0.f); o.w = fmaxf(o.w, 0.f);
            }
            *(float4*)(C + (size_t)row * N + bn + jh * 64 + (tx << 2)) = o;
        }
    }
}

// ---------------- SGEMM 64x64 tile (small GEMMs) ----------------
__global__ void sgemm64(const float* __restrict__ A, const float* __restrict__ W,
                        float* __restrict__ C, int M, int N, int K, int relu) {
    __shared__ __align__(16) float As[16][64];
    __shared__ __align__(16) float Bs[16][64];
    int tid = threadIdx.x;
    int tx = tid & 15, ty = tid >> 4;
    int bm = blockIdx.y << 6, bn = blockIdx.x << 6;

    float acc[4][4];
    #pragma unroll
    for (int i = 0; i < 4; i++)
        #pragma unroll
        for (int j = 0; j < 4; j++) acc[i][j] = 0.f;

    int am  = tid >> 2;
    int ak  = (tid & 3) << 2;
    int bk  = tid >> 4;
    int bn4 = (tid & 15) << 2;

    const float* Ap = A + (size_t)(bm + am) * K + ak;
    const float* Wp = W + (size_t)bk * N + bn + bn4;

    for (int k0 = 0; k0 < K; k0 += 16) {
        float4 a = *(const float4*)(Ap + k0);
        As[ak + 0][am] = a.x; As[ak + 1][am] = a.y;
        As[ak + 2][am] = a.z; As[ak + 3][am] = a.w;
        float4 b = *(const float4*)(Wp + (size_t)k0 * N);
        *(float4*)&Bs[bk][bn4] = b;
        __syncthreads();
        #pragma unroll
        for (int k = 0; k < 16; k++) {
            float4 ar = *(const float4*)&As[k][ty << 2];
            float4 br = *(const float4*)&Bs[k][tx << 2];
            float arr[4] = {ar.x, ar.y, ar.z, ar.w};
            float brr[4] = {br.x, br.y, br.z, br.w};
            #pragma unroll
            for (int i = 0; i < 4; i++)
                #pragma unroll
                for (int j = 0; j < 4; j++)
                    acc[i][j] += arr[i] * brr[j];
        }
        __syncthreads();
    }
    #pragma unroll
    for (int i = 0; i < 4; i++) {
        float4 o;
        o.x = acc[i][0]; o.y = acc[i][1]; o.z = acc[i][2]; o.w = acc[i][3];
        if (relu) {
            o.x = fmaxf(o.x, 0.f); o.y = fmaxf(o.y, 0.f);
            o.z = fmaxf(o.z, 0.f); o.w = fmaxf(o.w, 0.f);
        }
        *(float4*)(C + (size_t)(bm + (ty << 2) + i) * N + bn + (tx << 2)) = o;
    }
}

// ---------------- flash attention: one block per (b,h), K/V read once ----------------
// 256 threads, online softmax over F in chunks of FCH=128.
// smem: Qt[64][64] (d-major), Kt[64][FCH] (d-major), Vs[FCH][64], Ps[64][FCH], msk[FCH]
__global__ void flash_attn(const float* __restrict__ qb, const float* __restrict__ kb,
                           const float* __restrict__ vb, const int* __restrict__ mask,
                           float* __restrict__ out) {
    extern __shared__ float sh[];
    float* Qt = sh;                       // 64*64
    float* Kt = Qt + 64 * 64;             // 64*FCH
    float* Vs = Kt + 64 * FCH;            // FCH*64
    float* Ps = Vs + FCH * 64;            // 64*FCH
    int*   msk = (int*)(Ps + 64 * FCH);   // FCH

    int tid = threadIdx.x;
    int tx = tid & 15, ty = tid >> 4;
    int h = blockIdx.x & 7;
    int b = blockIdx.x >> 3;

    const size_t qbase = (size_t)b * Qq * DIMc + h * DHh;
    const size_t kbase = (size_t)b * Ff * DIMc + h * DHh;
    const int* mrow = mask + (size_t)b * Ff;

    // load Q (pre-scaled) transposed: Qt[d][q]
    #pragma unroll
    for (int rep = 0; rep < 4; rep++) {
        int idx = rep * 256 + tid;
        int qi = idx >> 4;
        int d4 = (idx & 15) << 2;
        float4 v = *(const float4*)(qb + qbase + (size_t)qi * DIMc + d4);
        Qt[(d4 + 0) * 64 + qi] = v.x * 0.125f;
        Qt[(d4 + 1) * 64 + qi] = v.y * 0.125f;
        Qt[(d4 + 2) * 64 + qi] = v.z * 0.125f;
        Qt[(d4 + 3) * 64 + qi] = v.w * 0.125f;
    }

    float m[4], l[4], O[4][4];
    #pragma unroll
    for (int i = 0; i < 4; i++) {
        m[i] = -INFINITY; l[i] = 0.f;
        #pragma unroll
        for (int j = 0; j < 4; j++) O[i][j] = 0.f;
    }

    for (int f0 = 0; f0 < Ff; f0 += FCH) {
        // load K chunk (transposed) and V chunk (direct) + mask
        #pragma unroll
        for (int rep = 0; rep < 8; rep++) {
            int idx = rep * 256 + tid;
            int f = idx >> 4;
            int d4 = (idx & 15) << 2;
            const float* src = kb + kbase + (size_t)(f0 + f) * DIMc + d4;
            float4 kv = *(const float4*)src;
            Kt[(d4 + 0) * FCH + f] = kv.x;
            Kt[(d4 + 1) * FCH + f] = kv.y;
            Kt[(d4 + 2) * FCH + f] = kv.z;
            Kt[(d4 + 3) * FCH + f] = kv.w;
            float4 vv = *(const float4*)(vb + kbase + (size_t)(f0 + f) * DIMc + d4);
            *(float4*)&Vs[f * 64 + d4] = vv;
        }
        if (tid < FCH) msk[tid] = mrow[f0 + tid];
        __syncthreads();

        // S[4][8]: rows 4ty+i, cols 8tx+j
        float S[4][8];
        #pragma unroll
        for (int i = 0; i < 4; i++)
            #pragma unroll
            for (int j = 0; j < 8; j++) S[i][j] = 0.f;
        #pragma unroll 4
        for (int d = 0; d < 64; d++) {
            float4 a  = *(const float4*)&Qt[d * 64 + (ty << 2)];
            float4 b0 = *(const float4*)&Kt[d * FCH + (tx << 3)];
            float4 b1 = *(const float4*)&Kt[d * FCH + (tx << 3) + 4];
            float ar[4] = {a.x, a.y, a.z, a.w};
            float br[8] = {b0.x, b0.y, b0.z, b0.w, b1.x, b1.y, b1.z, b1.w};
            #pragma unroll
            for (int i = 0; i < 4; i++)
                #pragma unroll
                for (int j = 0; j < 8; j++)
                    S[i][j] += ar[i] * br[j];
        }

        // mask
        int mj[8];
        #pragma unroll
        for (int j = 0; j < 8; j++) mj[j] = msk[(tx << 3) + j];
        #pragma unroll
        for (int j = 0; j < 8; j++)
            if (!mj[j]) {
                #pragma unroll
                for (int i = 0; i < 4; i++) S[i][j] = -INFINITY;
            }

        // online softmax update per row
        #pragma unroll
        for (int i = 0; i < 4; i++) {
            float rm = S[i][0];
            #pragma unroll
            for (int j = 1; j < 8; j++) rm = fmaxf(rm, S[i][j]);
            #pragma unroll
            for (int o = 1; o < 16; o <<= 1)
                rm = fmaxf(rm, __shfl_xor_sync(0xffffffffu, rm, o));
            float mn = fmaxf(m[i], rm);
            float sf = (mn == -INFINITY) ? 1.f : __expf(m[i] - mn);
            float rs = 0.f;
            #pragma unroll
            for (int j = 0; j < 8; j++) {
                float e = (S[i][j] == -INFINITY) ? 0.f : __expf(S[i][j] - mn);
                S[i][j] = e;
                rs += e;
            }
            #pragma unroll
            for (int o = 1; o < 16; o <<= 1)
                rs += __shfl_xor_sync(0xffffffffu, rs, o);
            l[i] = l[i] * sf + rs;
            m[i] = mn;
            #pragma unroll
            for (int j = 0; j < 4; j++) O[i][j] *= sf;
            // write P row
            float4 p0 = {S[i][0], S[i][1], S[i][2], S[i][3]};
            float4 p1 = {S[i][4], S[i][5], S[i][6], S[i][7]};
            *(float4*)&Ps[((ty << 2) + i) * FCH + (tx << 3)] = p0;
            *(float4*)&Ps[((ty << 2) + i) * FCH + (tx << 3) + 4] = p1;
        }
        __syncthreads();

        // O += P @ V : O rows 4ty+i, cols 4tx+j
        #pragma unroll 2
        for (int k4 = 0; k4 < FCH / 4; k4++) {
            float4 a[4], bV[4];
            #pragma unroll
            for (int i = 0; i < 4; i++)
                a[i] = *(const float4*)&Ps[((ty << 2) + i) * FCH + (k4 << 2)];
            #pragma unroll
            for (int kk = 0; kk < 4; kk++)
                bV[kk] = *(const float4*)&Vs[((k4 << 2) + kk) * 64 + (tx << 2)];
            #pragma unroll
            for (int i = 0; i < 4; i++) {
                float ai[4] = {a[i].x, a[i].y, a[i].z, a[i].w};
                #pragma unroll
                for (int kk = 0; kk < 4; kk++) {
                    float bb[4] = {bV[kk].x, bV[kk].y, bV[kk].z, bV[kk].w};
                    #pragma unroll
                    for (int j = 0; j < 4; j++)
                        O[i][j] += ai[kk] * bb[j];
                }
            }
        }
        __syncthreads();
    }

    // epilogue
    #pragma unroll
    for (int i = 0; i < 4; i++) {
        float inv = (l[i] > 0.f) ? (1.f / l[i]) : 0.f;
        float4 o;
        o.x = O[i][0] * inv; o.y = O[i][1] * inv;
        o.z = O[i][2] * inv; o.w = O[i][3] * inv;
        *(float4*)(out + qbase + (size_t)((ty << 2) + i) * DIMc + (tx << 2)) = o;
    }
}

// ---------------- launch ----------------
extern "C" void kernel_launch(void* const* d_in, const int* in_sizes, int n_in,
                              void* d_out, int out_size) {
    const float* features = (const float*)d_in[0];
    const float* latents  = (const float*)d_in[1];
    const int*   mask     = (const int*)  d_in[2];
    const float* gf  = (const float*)d_in[3];
    const float* bf  = (const float*)d_in[4];
    const float* gl  = (const float*)d_in[5];
    const float* bl  = (const float*)d_in[6];
    const float* Wq  = (const float*)d_in[7];
    const float* Wk  = (const float*)d_in[8];
    const float* Wv  = (const float*)d_in[9];
    const float* gff = (const float*)d_in[10];
    const float* bff = (const float*)d_in[11];
    const float* W1  = (const float*)d_in[12];
    const float* W2  = (const float*)d_in[13];
    float* out = (float*)d_out;

    float *xn, *latn, *q, *k, *v, *att, *ln2, *ffh;
    cudaGetSymbolAddress((void**)&xn,   g_xn);
    cudaGetSymbolAddress((void**)&latn, g_latn);
    cudaGetSymbolAddress((void**)&q,    g_q);
    cudaGetSymbolAddress((void**)&k,    g_k);
    cudaGetSymbolAddress((void**)&v,    g_v);
    cudaGetSymbolAddress((void**)&att,  g_att);
    cudaGetSymbolAddress((void**)&ln2,  g_ln2);
    cudaGetSymbolAddress((void**)&ffh,  g_ffh);

    const int FLASH_SMEM = (64 * 64 + 64 * FCH + FCH * 64 + 64 * FCH) * 4 + FCH * 4;
    cudaFuncSetAttribute(flash_attn, cudaFuncAttributeMaxDynamicSharedMemorySize, FLASH_SMEM);

    // layernorms
    ln_kernel<<<Bb * Ff, 128>>>(features, gf, bf, xn);
    ln_kernel<<<Bb * Qq, 128>>>(latents,  gl, bl, latn);

    // projections
    sgemm64 <<<dim3(DIMc / 64,  (Bb * Qq) / 64),  256>>>(latn, Wq, q, Bb * Qq, DIMc, DIMc, 0);
    sgemm128<<<dim3(DIMc / 128, (Bb * Ff) / 128), 256>>>(xn,   Wk, k, Bb * Ff, DIMc, DIMc, 0);
    sgemm128<<<dim3(DIMc / 128, (Bb * Ff) / 128), 256>>>(xn,   Wv, v, Bb * Ff, DIMc, DIMc, 0);

    // attention
    flash_attn<<<Bb * Hh, 256, FLASH_SMEM>>>(q, k, v, mask, att);

    // feed-forward
    ln_kernel<<<Bb * Qq, 128>>>(att, gff, bff, ln2);
    sgemm64<<<dim3(1024 / 64, (Bb * Qq) / 64), 256>>>(ln2, W1, ffh, Bb * Qq, 1024, DIMc, 1);
    sgemm64<<<dim3(DIMc / 64, (Bb * Qq) / 64), 256>>>(ffh, W2, out, Bb * Qq, DIMc, 1024, 0);
}

// round 6
// speedup vs baseline: 2.2170x; 1.3770x over previous
#include <cuda_runtime.h>
#include <cstdint>
#include <math.h>

#define Bb   16
#define Ff   4096
#define Qq   64
#define DIMc 512
#define Hh   8
#define DHh  64
#define FCH  128

// ---------------- scratch (device globals; no allocation allowed) ----------------
__device__ float g_xn  [(size_t)Bb * Ff * DIMc];
__device__ float g_latn[(size_t)Bb * Qq * DIMc];
__device__ float g_q   [(size_t)Bb * Qq * DIMc];
__device__ float g_k   [(size_t)Bb * Ff * DIMc];
__device__ float g_v   [(size_t)Bb * Ff * DIMc];
__device__ float g_att [(size_t)Bb * Qq * DIMc];
__device__ float g_ln2 [(size_t)Bb * Qq * DIMc];
__device__ float g_ffh [(size_t)Bb * Qq * 1024];

// ---------------- helpers ----------------
static __device__ __forceinline__ uint32_t smem_u32(const void* p) {
    uint32_t a;
    asm("{ .reg .u64 t; cvta.to.shared.u64 t, %1; cvt.u32.u64 %0, t; }" : "=r"(a) : "l"(p));
    return a;
}
static __device__ __forceinline__ void cpa16(uint32_t dst, const void* src) {
    asm volatile("cp.async.cg.shared.global [%0], [%1], 16;" :: "r"(dst), "l"(src));
}
#define CPA_COMMIT() asm volatile("cp.async.commit_group;" ::: "memory")
#define CPA_WAIT1()  asm volatile("cp.async.wait_group 1;" ::: "memory")

#define LDSM4(r0, r1, r2, r3, addr)                                        \
    asm volatile("ldmatrix.sync.aligned.m8n8.x4.shared.b16 {%0,%1,%2,%3}, [%4];" \
                 : "=r"(r0), "=r"(r1), "=r"(r2), "=r"(r3) : "r"(addr))

#define MMA_TF32(c, a0, a1, a2, a3, b0, b1)                                \
    asm volatile("mma.sync.aligned.m16n8k8.row.col.f32.tf32.tf32.f32 "     \
                 "{%0,%1,%2,%3}, {%4,%5,%6,%7}, {%8,%9}, {%0,%1,%2,%3};"   \
                 : "+f"((c)[0]), "+f"((c)[1]), "+f"((c)[2]), "+f"((c)[3])  \
                 : "r"(a0), "r"(a1), "r"(a2), "r"(a3), "r"(b0), "r"(b1))

// split f32 bits into tf32 hi (top-10 mantissa) and lo (exact residual)
static __device__ __forceinline__ void tf32_split(uint32_t a, uint32_t& hi, uint32_t& lo) {
    hi = a & 0xFFFFE000u;
    lo = __float_as_uint(__uint_as_float(a) - __uint_as_float(hi));
}

// ---------------- 3xTF32 mma.sync GEMM: C[M,N]=A[M,K]@W[K,N], 128x128 tile ----------------
// 256 threads (8 warps of 64x32). M,N % 128 == 0, K % 32 == 0.
#define A_STAGE_B  16384
#define B_ROW_F    136
#define B_STAGE_B  (32 * B_ROW_F * 4)      // 17408
#define STAGE_B    (A_STAGE_B + B_STAGE_B) // 33792
#define GEMM_SMEM  (3 * STAGE_B)           // 101376

__global__ void __launch_bounds__(256) mma_gemm(
    const float* __restrict__ A, const float* __restrict__ W,
    float* __restrict__ C, int M, int N, int K, int relu)
{
    extern __shared__ __align__(1024) char smem[];
    int tid = threadIdx.x;
    int lane = tid & 31, wid = tid >> 5;
    int bn = blockIdx.x << 7, bm = blockIdx.y << 7;
    uint32_t sbase = smem_u32(smem);

    int wm = (wid & 1) << 6;   // warp m offset: 0/64
    int wn = (wid >> 1) << 5;  // warp n offset: 0/32/64/96

    float acc[4][4][4];
    #pragma unroll
    for (int i = 0; i < 4; i++)
        #pragma unroll
        for (int j = 0; j < 4; j++)
            #pragma unroll
            for (int r = 0; r < 4; r++) acc[i][j][r] = 0.f;

    int nCh = K >> 5;

    auto issue = [&](int p, int s) {
        uint32_t aS = sbase + s * STAGE_B;
        uint32_t bS = aS + A_STAGE_B;
        int k0 = p << 5;
        #pragma unroll
        for (int r = 0; r < 4; r++) {
            int c = r * 256 + tid;
            int m = c >> 3, kq = c & 7;
            uint32_t off = m * 128 + (kq << 4);
            uint32_t sw = off ^ ((off >> 3) & 0x70);
            cpa16(aS + sw, A + (size_t)(bm + m) * K + k0 + (kq << 2));
        }
        #pragma unroll
        for (int r = 0; r < 4; r++) {
            int c = r * 256 + tid;
            int k = c >> 5, n16 = c & 31;
            cpa16(bS + k * (B_ROW_F * 4) + (n16 << 4),
                  W + (size_t)(k0 + k) * N + bn + (n16 << 2));
        }
        CPA_COMMIT();
    };

    issue(0, 0);
    if (nCh > 1) issue(1, 1); else CPA_COMMIT();

    int quad = lane >> 3, rr = lane & 7;
    int lrow = ((quad & 1) << 3) + rr;
    int lcol = quad >> 1;

    for (int p = 0; p < nCh; p++) {
        CPA_WAIT1();
        __syncthreads();
        int s = p % 3;
        uint32_t aS = sbase + s * STAGE_B;
        uint32_t bS = aS + A_STAGE_B;

        uint32_t bBase = bS + ((lane & 3) * B_ROW_F + wn + (lane >> 2)) * 4;

        #pragma unroll
        for (int j = 0; j < 4; j++) {        // 4 k-steps of 8
            uint32_t ah[4][4], al[4][4];
            #pragma unroll
            for (int mt = 0; mt < 4; mt++) {
                uint32_t raw[4];
                uint32_t off = (uint32_t)(wm + mt * 16 + lrow) * 128 + ((j << 1) + lcol) * 16;
                uint32_t sw = off ^ ((off >> 3) & 0x70);
                LDSM4(raw[0], raw[1], raw[2], raw[3], aS + sw);
                #pragma unroll
                for (int r = 0; r < 4; r++) tf32_split(raw[r], ah[mt][r], al[mt][r]);
            }
            uint32_t bh[4][2], bl[4][2];
            uint32_t bj = bBase + (j << 3) * (B_ROW_F * 4);
            #pragma unroll
            for (int nt = 0; nt < 4; nt++) {
                uint32_t b0, b1;
                asm volatile("ld.shared.b32 %0, [%1];" : "=r"(b0) : "r"(bj + nt * 32));
                asm volatile("ld.shared.b32 %0, [%1];" : "=r"(b1) : "r"(bj + nt * 32 + 4 * (B_ROW_F * 4)));
                tf32_split(b0, bh[nt][0], bl[nt][0]);
                tf32_split(b1, bh[nt][1], bl[nt][1]);
            }
            #pragma unroll
            for (int mt = 0; mt < 4; mt++)
                #pragma unroll
                for (int nt = 0; nt < 4; nt++) {
                    MMA_TF32(acc[mt][nt], ah[mt][0], ah[mt][1], ah[mt][2], ah[mt][3],
                             bh[nt][0], bh[nt][1]);
                    MMA_TF32(acc[mt][nt], ah[mt][0], ah[mt][1], ah[mt][2], ah[mt][3],
                             bl[nt][0], bl[nt][1]);
                    MMA_TF32(acc[mt][nt], al[mt][0], al[mt][1], al[mt][2], al[mt][3],
                             bh[nt][0], bh[nt][1]);
                }
        }
        if (p + 2 < nCh) issue(p + 2, (p + 2) % 3);
        else CPA_COMMIT();
    }

    int r0 = bm + wm + (lane >> 2);
    int cc = bn + wn + ((lane & 3) << 1);
    #pragma unroll
    for (int mt = 0; mt < 4; mt++) {
        #pragma unroll
        for (int nt = 0; nt < 4; nt++) {
            float2 lo = {acc[mt][nt][0], acc[mt][nt][1]};
            float2 hi = {acc[mt][nt][2], acc[mt][nt][3]};
            if (relu) {
                lo.x = fmaxf(lo.x, 0.f); lo.y = fmaxf(lo.y, 0.f);
                hi.x = fmaxf(hi.x, 0.f); hi.y = fmaxf(hi.y, 0.f);
            }
            *(float2*)(C + (size_t)(r0 + mt * 16) * N + cc + nt * 8) = lo;
            *(float2*)(C + (size_t)(r0 + mt * 16 + 8) * N + cc + nt * 8) = hi;
        }
    }
}

// ---------------- LayerNorm: one block (128 threads) per row of 512 ----------------
__global__ void ln_kernel(const float* __restrict__ x, const float* __restrict__ g,
                          const float* __restrict__ beta, float* __restrict__ y) {
    __shared__ float sm[4];
    size_t row = blockIdx.x;
    int t = threadIdx.x;
    float4 v = ((const float4*)(x + row * DIMc))[t];
    float s = v.x + v.y + v.z + v.w;
    #pragma unroll
    for (int o = 16; o; o >>= 1) s += __shfl_xor_sync(0xffffffffu, s, o);
    if ((t & 31) == 0) sm[t >> 5] = s;
    __syncthreads();
    float mean = (sm[0] + sm[1] + sm[2] + sm[3]) * (1.0f / DIMc);
    __syncthreads();
    float dx = v.x - mean, dy = v.y - mean, dz = v.z - mean, dw = v.w - mean;
    float sq = dx * dx + dy * dy + dz * dz + dw * dw;
    #pragma unroll
    for (int o = 16; o; o >>= 1) sq += __shfl_xor_sync(0xffffffffu, sq, o);
    if ((t & 31) == 0) sm[t >> 5] = sq;
    __syncthreads();
    float var = (sm[0] + sm[1] + sm[2] + sm[3]) * (1.0f / DIMc);
    float rstd = rsqrtf(var + 1e-5f);
    float4 gg = ((const float4*)g)[t];
    float4 bb = ((const float4*)beta)[t];
    float4 o4;
    o4.x = dx * rstd * gg.x + bb.x;
    o4.y = dy * rstd * gg.y + bb.y;
    o4.z = dz * rstd * gg.z + bb.z;
    o4.w = dw * rstd * gg.w + bb.w;
    ((float4*)(y + row * DIMc))[t] = o4;
}

// ---------------- flash attention: one block per (b,h), K/V read once ----------------
__global__ void flash_attn(const float* __restrict__ qb, const float* __restrict__ kb,
                           const float* __restrict__ vb, const int* __restrict__ mask,
                           float* __restrict__ out) {
    extern __shared__ float sh[];
    float* Qt = sh;
    float* Kt = Qt + 64 * 64;
    float* Vs = Kt + 64 * FCH;
    float* Ps = Vs + FCH * 64;
    int*   msk = (int*)(Ps + 64 * FCH);

    int tid = threadIdx.x;
    int tx = tid & 15, ty = tid >> 4;
    int h = blockIdx.x & 7;
    int b = blockIdx.x >> 3;

    const size_t qbase = (size_t)b * Qq * DIMc + h * DHh;
    const size_t kbase = (size_t)b * Ff * DIMc + h * DHh;
    const int* mrow = mask + (size_t)b * Ff;

    #pragma unroll
    for (int rep = 0; rep < 4; rep++) {
        int idx = rep * 256 + tid;
        int qi = idx >> 4;
        int d4 = (idx & 15) << 2;
        float4 v = *(const float4*)(qb + qbase + (size_t)qi * DIMc + d4);
        Qt[(d4 + 0) * 64 + qi] = v.x * 0.125f;
        Qt[(d4 + 1) * 64 + qi] = v.y * 0.125f;
        Qt[(d4 + 2) * 64 + qi] = v.z * 0.125f;
        Qt[(d4 + 3) * 64 + qi] = v.w * 0.125f;
    }

    float m[4], l[4], O[4][4];
    #pragma unroll
    for (int i = 0; i < 4; i++) {
        m[i] = -INFINITY; l[i] = 0.f;
        #pragma unroll
        for (int j = 0; j < 4; j++) O[i][j] = 0.f;
    }

    for (int f0 = 0; f0 < Ff; f0 += FCH) {
        #pragma unroll
        for (int rep = 0; rep < 8; rep++) {
            int idx = rep * 256 + tid;
            int f = idx >> 4;
            int d4 = (idx & 15) << 2;
            const float* src = kb + kbase + (size_t)(f0 + f) * DIMc + d4;
            float4 kv = *(const float4*)src;
            Kt[(d4 + 0) * FCH + f] = kv.x;
            Kt[(d4 + 1) * FCH + f] = kv.y;
            Kt[(d4 + 2) * FCH + f] = kv.z;
            Kt[(d4 + 3) * FCH + f] = kv.w;
            float4 vv = *(const float4*)(vb + kbase + (size_t)(f0 + f) * DIMc + d4);
            *(float4*)&Vs[f * 64 + d4] = vv;
        }
        if (tid < FCH) msk[tid] = mrow[f0 + tid];
        __syncthreads();

        float S[4][8];
        #pragma unroll
        for (int i = 0; i < 4; i++)
            #pragma unroll
            for (int j = 0; j < 8; j++) S[i][j] = 0.f;
        #pragma unroll 4
        for (int d = 0; d < 64; d++) {
            float4 a  = *(const float4*)&Qt[d * 64 + (ty << 2)];
            float4 b0 = *(const float4*)&Kt[d * FCH + (tx << 3)];
            float4 b1 = *(const float4*)&Kt[d * FCH + (tx << 3) + 4];
            float ar[4] = {a.x, a.y, a.z, a.w};
            float br[8] = {b0.x, b0.y, b0.z, b0.w, b1.x, b1.y, b1.z, b1.w};
            #pragma unroll
            for (int i = 0; i < 4; i++)
                #pragma unroll
                for (int j = 0; j < 8; j++)
                    S[i][j] += ar[i] * br[j];
        }

        int mj[8];
        #pragma unroll
        for (int j = 0; j < 8; j++) mj[j] = msk[(tx << 3) + j];
        #pragma unroll
        for (int j = 0; j < 8; j++)
            if (!mj[j]) {
                #pragma unroll
                for (int i = 0; i < 4; i++) S[i][j] = -INFINITY;
            }

        #pragma unroll
        for (int i = 0; i < 4; i++) {
            float rm = S[i][0];
            #pragma unroll
            for (int j = 1; j < 8; j++) rm = fmaxf(rm, S[i][j]);
            #pragma unroll
            for (int o = 1; o < 16; o <<= 1)
                rm = fmaxf(rm, __shfl_xor_sync(0xffffffffu, rm, o));
            float mn = fmaxf(m[i], rm);
            float sf = (mn == -INFINITY) ? 1.f : __expf(m[i] - mn);
            float rs = 0.f;
            #pragma unroll
            for (int j = 0; j < 8; j++) {
                float e = (S[i][j] == -INFINITY) ? 0.f : __expf(S[i][j] - mn);
                S[i][j] = e;
                rs += e;
            }
            #pragma unroll
            for (int o = 1; o < 16; o <<= 1)
                rs += __shfl_xor_sync(0xffffffffu, rs, o);
            l[i] = l[i] * sf + rs;
            m[i] = mn;
            #pragma unroll
            for (int j = 0; j < 4; j++) O[i][j] *= sf;
            float4 p0 = {S[i][0], S[i][1], S[i][2], S[i][3]};
            float4 p1 = {S[i][4], S[i][5], S[i][6], S[i][7]};
            *(float4*)&Ps[((ty << 2) + i) * FCH + (tx << 3)] = p0;
            *(float4*)&Ps[((ty << 2) + i) * FCH + (tx << 3) + 4] = p1;
        }
        __syncthreads();

        #pragma unroll 2
        for (int k4 = 0; k4 < FCH / 4; k4++) {
            float4 a[4], bV[4];
            #pragma unroll
            for (int i = 0; i < 4; i++)
                a[i] = *(const float4*)&Ps[((ty << 2) + i) * FCH + (k4 << 2)];
            #pragma unroll
            for (int kk = 0; kk < 4; kk++)
                bV[kk] = *(const float4*)&Vs[((k4 << 2) + kk) * 64 + (tx << 2)];
            #pragma unroll
            for (int i = 0; i < 4; i++) {
                float ai[4] = {a[i].x, a[i].y, a[i].z, a[i].w};
                #pragma unroll
                for (int kk = 0; kk < 4; kk++) {
                    float bb[4] = {bV[kk].x, bV[kk].y, bV[kk].z, bV[kk].w};
                    #pragma unroll
                    for (int j = 0; j < 4; j++)
                        O[i][j] += ai[kk] * bb[j];
                }
            }
        }
        __syncthreads();
    }

    #pragma unroll
    for (int i = 0; i < 4; i++) {
        float inv = (l[i] > 0.f) ? (1.f / l[i]) : 0.f;
        float4 o;
        o.x = O[i][0] * inv; o.y = O[i][1] * inv;
        o.z = O[i][2] * inv; o.w = O[i][3] * inv;
        *(float4*)(out + qbase + (size_t)((ty << 2) + i) * DIMc + (tx << 2)) = o;
    }
}

// ---------------- launch ----------------
extern "C" void kernel_launch(void* const* d_in, const int* in_sizes, int n_in,
                              void* d_out, int out_size) {
    const float* features = (const float*)d_in[0];
    const float* latents  = (const float*)d_in[1];
    const int*   mask     = (const int*)  d_in[2];
    const float* gf  = (const float*)d_in[3];
    const float* bf  = (const float*)d_in[4];
    const float* gl  = (const float*)d_in[5];
    const float* bl  = (const float*)d_in[6];
    const float* Wq  = (const float*)d_in[7];
    const float* Wk  = (const float*)d_in[8];
    const float* Wv  = (const float*)d_in[9];
    const float* gff = (const float*)d_in[10];
    const float* bff = (const float*)d_in[11];
    const float* W1  = (const float*)d_in[12];
    const float* W2  = (const float*)d_in[13];
    float* out = (float*)d_out;

    float *xn, *latn, *q, *k, *v, *att, *ln2, *ffh;
    cudaGetSymbolAddress((void**)&xn,   g_xn);
    cudaGetSymbolAddress((void**)&latn, g_latn);
    cudaGetSymbolAddress((void**)&q,    g_q);
    cudaGetSymbolAddress((void**)&k,    g_k);
    cudaGetSymbolAddress((void**)&v,    g_v);
    cudaGetSymbolAddress((void**)&att,  g_att);
    cudaGetSymbolAddress((void**)&ln2,  g_ln2);
    cudaGetSymbolAddress((void**)&ffh,  g_ffh);

    const int FLASH_SMEM = (64 * 64 + 64 * FCH + FCH * 64 + 64 * FCH) * 4 + FCH * 4;
    cudaFuncSetAttribute(flash_attn, cudaFuncAttributeMaxDynamicSharedMemorySize, FLASH_SMEM);
    cudaFuncSetAttribute(mma_gemm, cudaFuncAttributeMaxDynamicSharedMemorySize, GEMM_SMEM);

    // layernorms
    ln_kernel<<<Bb * Ff, 128>>>(features, gf, bf, xn);
    ln_kernel<<<Bb * Qq, 128>>>(latents,  gl, bl, latn);

    // projections (3xTF32 mma.sync)
    mma_gemm<<<dim3(DIMc / 128, (Bb * Qq) / 128), 256, GEMM_SMEM>>>(latn, Wq, q, Bb * Qq, DIMc, DIMc, 0);
    mma_gemm<<<dim3(DIMc / 128, (Bb * Ff) / 128), 256, GEMM_SMEM>>>(xn,   Wk, k, Bb * Ff, DIMc, DIMc, 0);
    mma_gemm<<<dim3(DIMc / 128, (Bb * Ff) / 128), 256, GEMM_SMEM>>>(xn,   Wv, v, Bb * Ff, DIMc, DIMc, 0);

    // attention
    flash_attn<<<Bb * Hh, 256, FLASH_SMEM>>>(q, k, v, mask, att);

    // feed-forward (3xTF32 mma.sync)
    ln_kernel<<<Bb * Qq, 128>>>(att, gff, bff, ln2);
    mma_gemm<<<dim3(1024 / 128, (Bb * Qq) / 128), 256, GEMM_SMEM>>>(ln2, W1, ffh, Bb * Qq, 1024, DIMc, 1);
    mma_gemm<<<dim3(DIMc / 128, (Bb * Qq) / 128), 256, GEMM_SMEM>>>(ffh, W2, out, Bb * Qq, DIMc, 1024, 0);
}